// round 14
// baseline (speedup 1.0000x reference)
#include <cuda_runtime.h>
#include <cuda_bf16.h>

#define NUM_CHIPS 4
#define N_EXPERTS 32
#define TOP_K 4
#define SEQ 1024
#define HIDDEN 2048
#define MAX_TOK 1024
#define META_LEN 8
#define NPC (SEQ * TOP_K)            /* 4096 assignments per chip  */
#define NA (NUM_CHIPS * NPC)         /* 16384 total assignments    */
#define NROWS (N_EXPERTS * MAX_TOK)  /* 32768 output rows          */
#define NWGRP (NA / 32)              /* 512 assignment warp-groups */

#define BLOCKS 1024                  /* must ALL be co-resident    */
#define THREADS 256
#define NTHR (BLOCKS * THREADS)      /* 262144                     */
#define BAR_MOD (3u * BLOCKS)        /* 3 barriers per launch      */

#define V4_PER_ROW (HIDDEN / 4)      /* 512 float4 per row         */
#define TOTAL_V4 (NROWS * V4_PER_ROW)        /* 16777216           */
#define ITERS (TOTAL_V4 / NTHR)              /* 64 per thread      */

/* scratch — no allocations allowed; every used cell rewritten per run */
__device__ int g_wcnt[NWGRP * N_EXPERTS];   /* [wg][e] per-warp-group counts */
__device__ int g_woff[NWGRP * N_EXPERTS];   /* [wg][e] global exclusive pfx  */
__device__ int g_total[N_EXPERTS];
__device__ int2 g_pack[NROWS];              /* row -> {src | -1, assignment} */
__device__ unsigned g_bar;                  /* monotonic barrier counter     */

/* ------------------------------------------------------------------ */
/* Grid barrier over BLOCKS co-resident blocks. Each launch adds
   exactly BAR_MOD arrivals; phase boundaries are strict (a block can
   only reach barrier p after barrier p-1 released), so
   base = old - old % BAR_MOD is replay-deterministic. phase = 1..3.   */
__device__ __forceinline__ void gbar(unsigned phase) {
    __syncthreads();
    if (threadIdx.x == 0) {
        __threadfence();
        const unsigned old = atomicAdd(&g_bar, 1u);
        const unsigned target = (old - old % BAR_MOD) + phase * BLOCKS;
        while (*(volatile unsigned*)&g_bar < target) {}
        __threadfence();
    }
    __syncthreads();
}

/* ------------------------------------------------------------------ */
/* THE kernel: plan (3 phases, 2 barriers) then streaming copy.
   1024 blocks x 256 threads, forced >=8 blocks/SM so all co-resident. */
__global__ void __launch_bounds__(THREADS, 8)
k_all(const float4* __restrict__ x4,
      const float* __restrict__ wts,
      const int* __restrict__ indices,
      float4* __restrict__ buf4,
      float* __restrict__ meta,
      float* __restrict__ out_cnt) {
    const int b = blockIdx.x, tid = threadIdx.x;
    const int lane = tid & 31;

    /* ---- P1: per-warp counts + intra-warp stable rank (registers) ---- */
    int e = -1, lrank = 0;
    const int a = b * THREADS + tid;                 /* assignment id (b<64) */
    if (b < 64) {
        e = indices[a];
        const unsigned mask = __match_any_sync(0xffffffffu, e);
        lrank = __popc(mask & ((1u << lane) - 1u));
        int cnt = 0;
#pragma unroll
        for (int x = 0; x < N_EXPERTS; x++) {
            const unsigned m = __ballot_sync(0xffffffffu, e == x);
            if (lane == x) cnt = __popc(m);
        }
        g_wcnt[(a >> 5) * N_EXPERTS + lane] = cnt;   /* coalesced */
    }

    gbar(1);

    /* ---- P2: per-expert exclusive scan over the 512 warp-groups ---- */
    if (b >= 64 && b < 64 + N_EXPERTS) {
        __shared__ int wsum[8];
        const int eb = b - 64;
        const int w = tid >> 5;
        const int v0 = g_wcnt[(tid * 2 + 0) * N_EXPERTS + eb];
        const int v1 = g_wcnt[(tid * 2 + 1) * N_EXPERTS + eb];
        const int s = v0 + v1;
        int incl = s;
#pragma unroll
        for (int d = 1; d < 32; d <<= 1) {
            const int n = __shfl_up_sync(0xffffffffu, incl, d);
            if (lane >= d) incl += n;
        }
        if (lane == 31) wsum[w] = incl;
        __syncthreads();
        int base = 0;
#pragma unroll
        for (int ww = 0; ww < 8; ww++) if (ww < w) base += wsum[ww];
        const int excl = base + incl - s;
        g_woff[(tid * 2 + 0) * N_EXPERTS + eb] = excl;
        g_woff[(tid * 2 + 1) * N_EXPERTS + eb] = excl + v0;
        if (tid == THREADS - 1) {
            const int tot = base + incl;
            g_total[eb] = tot;
            out_cnt[eb] = (float)tot;
        }
    }

    gbar(2);

    /* ---- P3: pack table ---- */
    if (b < 64) {                                    /* filled rows */
        const int c = a >> 12, n = a & (NPC - 1);
        const int tok = n >> 2;
        const int row = e * MAX_TOK + g_woff[(a >> 5) * N_EXPERTS + e] + lrank;
        g_pack[row] = make_int2(c * SEQ + tok, a);
    } else if (b < 64 + 128) {                       /* tail rows -> {-1,-1} */
        const int row = (b - 64) * THREADS + tid;
        const int ee = row >> 10, r = row & (MAX_TOK - 1);
        if (r >= g_total[ee]) g_pack[row] = make_int2(-1, -1);
    }

    gbar(3);

    /* ---- Copy: flat grid-stride over all 16.7M float4 + meta ---- */
    const unsigned gtid = (unsigned)b * THREADS + tid;
    const bool do_meta = (gtid & (V4_PER_ROW - 1)) == 0u;  /* 512 threads */
#pragma unroll 4
    for (int it = 0; it < ITERS; it++) {
        const unsigned i = (unsigned)it * NTHR + gtid;
        const unsigned row = i >> 9;
        const int2 p = __ldg(&g_pack[row]);          /* warp-uniform, L1-hot */
        float4 v = make_float4(0.f, 0.f, 0.f, 0.f);
        if (p.x >= 0)
            v = __ldg(&x4[(unsigned)p.x * V4_PER_ROW + (i & (V4_PER_ROW - 1))]);
        buf4[i] = v;
        if (do_meta) {
            float4* m = (float4*)(meta + (size_t)row * META_LEN);
            if (p.x >= 0) {
                const int aa = p.y;
                const int c = aa >> 12, n = aa & (NPC - 1);
                const int tok = n >> 2, kk = n & (TOP_K - 1);
                const int ee = (int)(row >> 10);
                __nv_bfloat16 wb = __float2bfloat16(__ldg(&wts[aa]));  /* RNE */
                const int bits = (int)__bfloat16_as_short(wb);         /* sext */
                m[0] = make_float4((float)c, (float)tok, (float)kk, (float)ee);
                m[1] = make_float4((float)bits, 0.f, 0.f, 0.f);
            } else {
                const float4 neg = make_float4(-1.f, -1.f, -1.f, -1.f);
                m[0] = neg; m[1] = neg;
            }
        }
    }
}

/* ------------------------------------------------------------------ */
extern "C" void kernel_launch(void* const* d_in, const int* in_sizes, int n_in,
                              void* d_out, int out_size) {
    const float* x   = (const float*)d_in[0];
    const float* w   = (const float*)d_in[1];
    const int*   idx = (const int*)d_in[2];

    float* out  = (float*)d_out;
    float* buf  = out;                                                   /* 32*1024*2048 */
    float* meta = out + (size_t)NROWS * HIDDEN;                          /* 32*1024*8    */
    float* cnt  = meta + (size_t)NROWS * META_LEN;                       /* 32           */

    k_all<<<BLOCKS, THREADS>>>((const float4*)x, w, idx, (float4*)buf, meta, cnt);
}

// round 15
// speedup vs baseline: 1.2632x; 1.2632x over previous
#include <cuda_runtime.h>
#include <cuda_bf16.h>

#define NUM_CHIPS 4
#define N_EXPERTS 32
#define TOP_K 4
#define SEQ 1024
#define HIDDEN 2048
#define MAX_TOK 1024
#define META_LEN 8
#define NPC (SEQ * TOP_K)            /* 4096 assignments per chip  */
#define NA (NUM_CHIPS * NPC)         /* 16384 total assignments    */
#define NROWS (N_EXPERTS * MAX_TOK)  /* 32768 output rows          */
#define NWGRP (NA / 32)              /* 512 assignment warp-groups */

#define PLAN_BLOCKS 256
#define PLAN_THREADS 256

#define V4_PER_ROW (HIDDEN / 4)      /* 512 float4 per row  */
#define COPY_THREADS 128             /* one block per row; 64 B/thread */

/* scratch — no allocations allowed; every used cell rewritten per run */
__device__ int g_wcnt[NWGRP * N_EXPERTS];   /* [wg][e] per-warp-group counts */
__device__ int g_woff[NWGRP * N_EXPERTS];   /* [wg][e] global exclusive pfx  */
__device__ int g_total[N_EXPERTS];
__device__ int2 g_pack[NROWS];              /* row -> {src | -1, assignment} */
__device__ unsigned g_bar;                  /* monotonic barrier counter     */

/* ------------------------------------------------------------------ */
/* 256-bit global memory ops (sm_100+): LDG.256 / STG.256.             */
__device__ __forceinline__ void ldg256(const float4* p, float4& a, float4& b) {
    asm volatile("ld.global.nc.v8.f32 {%0,%1,%2,%3,%4,%5,%6,%7}, [%8];"
                 : "=f"(a.x), "=f"(a.y), "=f"(a.z), "=f"(a.w),
                   "=f"(b.x), "=f"(b.y), "=f"(b.z), "=f"(b.w)
                 : "l"(p));
}
__device__ __forceinline__ void stg256(float4* p, const float4& a, const float4& b) {
    asm volatile("st.global.v8.f32 [%0], {%1,%2,%3,%4,%5,%6,%7,%8};"
                 :: "l"(p),
                    "f"(a.x), "f"(a.y), "f"(a.z), "f"(a.w),
                    "f"(b.x), "f"(b.y), "f"(b.z), "f"(b.w)
                 : "memory");
}

/* ------------------------------------------------------------------ */
/* Grid barrier across PLAN_BLOCKS co-resident blocks (monotonic,
   replay-deterministic: each launch adds exactly 2*PLAN_BLOCKS).      */
__device__ __forceinline__ void plan_barrier(int phase) {
    __syncthreads();
    if (threadIdx.x == 0) {
        __threadfence();
        const unsigned old = atomicAdd(&g_bar, 1u);
        const unsigned base = old & ~(2u * PLAN_BLOCKS - 1u);
        const unsigned target = base + (unsigned)phase * PLAN_BLOCKS;
        while (*(volatile unsigned*)&g_bar < target) {}
        __threadfence();
    }
    __syncthreads();
}

/* ------------------------------------------------------------------ */
/* Plan kernel (proven, R11/R13): 256 blocks x 256 threads.
   P1: blocks 0..63  per-warp counts + intra-warp rank (registers).
   P2: blocks 64..95 per-expert scan -> woff/totals/counters.
   P3: blocks 0..63 filled g_pack; blocks 64..191 tail {-1,-1}.        */
__global__ void __launch_bounds__(PLAN_THREADS) k_plan(const int* __restrict__ indices,
                                                       float* __restrict__ out_cnt) {
    __shared__ int wsum[8];
    const int b = blockIdx.x, tid = threadIdx.x;
    const int lane = tid & 31;

    int e = -1, lrank = 0;
    const int t = b * PLAN_THREADS + tid;
    if (b < 64) {
        e = indices[t];
        const unsigned mask = __match_any_sync(0xffffffffu, e);
        lrank = __popc(mask & ((1u << lane) - 1u));
        int cnt = 0;
#pragma unroll
        for (int x = 0; x < N_EXPERTS; x++) {
            const unsigned m = __ballot_sync(0xffffffffu, e == x);
            if (lane == x) cnt = __popc(m);
        }
        g_wcnt[(t >> 5) * N_EXPERTS + lane] = cnt;
    }

    plan_barrier(1);

    if (b >= 64 && b < 64 + N_EXPERTS) {
        const int eb = b - 64;
        const int w = tid >> 5;
        const int v0 = g_wcnt[(tid * 2 + 0) * N_EXPERTS + eb];
        const int v1 = g_wcnt[(tid * 2 + 1) * N_EXPERTS + eb];
        const int s = v0 + v1;
        int incl = s;
#pragma unroll
        for (int d = 1; d < 32; d <<= 1) {
            const int n = __shfl_up_sync(0xffffffffu, incl, d);
            if (lane >= d) incl += n;
        }
        if (lane == 31) wsum[w] = incl;
        __syncthreads();
        int base = 0;
#pragma unroll
        for (int ww = 0; ww < 8; ww++) if (ww < w) base += wsum[ww];
        const int excl = base + incl - s;
        g_woff[(tid * 2 + 0) * N_EXPERTS + eb] = excl;
        g_woff[(tid * 2 + 1) * N_EXPERTS + eb] = excl + v0;
        if (tid == PLAN_THREADS - 1) {
            const int tot = base + incl;
            g_total[eb] = tot;
            out_cnt[eb] = (float)tot;
        }
    }

    plan_barrier(2);

    if (b < 64) {
        const int c = t >> 12, n = t & (NPC - 1);
        const int tok = n >> 2;
        const int row = e * MAX_TOK + g_woff[(t >> 5) * N_EXPERTS + e] + lrank;
        g_pack[row] = make_int2(c * SEQ + tok, t);
    } else if (b < 64 + 128) {
        const int row = (b - 64) * PLAN_THREADS + tid;
        const int ee = row >> 10, r = row & (MAX_TOK - 1);
        if (r >= g_total[ee]) g_pack[row] = make_int2(-1, -1);
    }
}

/* ------------------------------------------------------------------ */
/* Copy kernel: one 128-thread block per output row, 256-bit accesses.
   Thread t owns bytes [t*32, t*32+32) and [4096+t*32, ...): each warp
   instruction covers 1024B contiguous. Filled: 2 LDG.256 + 2 STG.256;
   zero: 2 STG.256. Meta by thread 0.                                  */
__global__ void __launch_bounds__(COPY_THREADS) k_copy(const float4* __restrict__ x4,
                                                       const float* __restrict__ wts,
                                                       float* __restrict__ meta,
                                                       float4* __restrict__ buf4) {
    const unsigned row = blockIdx.x;
    const unsigned t = threadIdx.x;
    const int2 p = __ldg(&g_pack[row]);              /* broadcast */
    float4* dst = buf4 + row * V4_PER_ROW + t * 2;   /* 32B-aligned */

    if (p.x >= 0) {
        const float4* src = x4 + (unsigned)p.x * V4_PER_ROW + t * 2;
        float4 a0, b0, a1, b1;
        ldg256(src, a0, b0);
        ldg256(src + 256, a1, b1);                   /* +4096 B */
        stg256(dst, a0, b0);
        stg256(dst + 256, a1, b1);
        if (t == 0) {
            const int a = p.y;
            const int c = a >> 12, n = a & (NPC - 1);
            const int tok = n >> 2, kk = n & (TOP_K - 1);
            const int e = (int)(row >> 10);
            __nv_bfloat16 wb = __float2bfloat16(__ldg(&wts[a]));  /* RNE */
            const int bits = (int)__bfloat16_as_short(wb);        /* sext */
            float4* m = (float4*)(meta + (size_t)row * META_LEN);
            m[0] = make_float4((float)c, (float)tok, (float)kk, (float)e);
            m[1] = make_float4((float)bits, 0.f, 0.f, 0.f);
        }
    } else {
        const float4 z = make_float4(0.f, 0.f, 0.f, 0.f);
        stg256(dst, z, z);
        stg256(dst + 256, z, z);
        if (t == 0) {
            float4* m = (float4*)(meta + (size_t)row * META_LEN);
            const float4 neg = make_float4(-1.f, -1.f, -1.f, -1.f);
            m[0] = neg; m[1] = neg;
        }
    }
}

/* ------------------------------------------------------------------ */
extern "C" void kernel_launch(void* const* d_in, const int* in_sizes, int n_in,
                              void* d_out, int out_size) {
    const float* x   = (const float*)d_in[0];
    const float* w   = (const float*)d_in[1];
    const int*   idx = (const int*)d_in[2];

    float* out  = (float*)d_out;
    float* buf  = out;                                                   /* 32*1024*2048 */
    float* meta = out + (size_t)NROWS * HIDDEN;                          /* 32*1024*8    */
    float* cnt  = meta + (size_t)NROWS * META_LEN;                       /* 32           */

    k_plan<<<PLAN_BLOCKS, PLAN_THREADS>>>(idx, cnt);
    k_copy<<<NROWS, COPY_THREADS>>>((const float4*)x, w, meta, (float4*)buf);
}